// round 9
// baseline (speedup 1.0000x reference)
#include <cuda_runtime.h>
#include <cuda_bf16.h>
#include <cuda_fp16.h>
#include <math.h>
#include <stdint.h>

// Problem dims (fixed)
#define BB 4
#define SS 2048
#define DD 1024
#define MS (BB*SS)          // 8192 rows total
#define OUT_ELEMS (MS*DD)

#define NPERS 296           // persistent grid: 2 CTAs/SM x 148 SMs

// --- bf16 split GEMM smem geometry: rows hold hi(64B)|lo(64B), stride 144B ---
#define ROWB   144
#define ATILEB (128*ROWB)
#define STAGEB (2*ATILEB)              // A + B tile = 36864 B
#define NSTAGE 3
#define SMEMB  (NSTAGE*STAGEB)         // 110592 B -> 2 CTAs/SM

// --- fp16 single GEMM smem geometry: rows 64B data + 16B pad -> 80B ---
#define ROWB2   80
#define ATIL2   (128*ROWB2)
#define STAGE2  (2*ATIL2)              // 20480 B
#define SMEM2   (NSTAGE*STAGE2)        // 61440 B

// ---------------------------------------------------------------------------
// PTX helpers (sm_80-level only: cp.async, ldmatrix, mma.sync)
// ---------------------------------------------------------------------------
__device__ __forceinline__ uint32_t smem_u32(const void* p) {
    uint32_t a;
    asm("{ .reg .u64 t; cvta.to.shared.u64 t, %1; cvt.u32.u64 %0, t; }" : "=r"(a) : "l"(p));
    return a;
}
#define CP16(d, s) asm volatile("cp.async.cg.shared.global [%0], [%1], 16;" :: "r"(d), "l"(s))
#define CPCOMMIT() asm volatile("cp.async.commit_group;" ::: "memory")
#define CPWAIT(n)  asm volatile("cp.async.wait_group %0;" :: "n"(n) : "memory")

__device__ __forceinline__ void ldsm4(uint32_t* r, uint32_t a) {
    asm volatile("ldmatrix.sync.aligned.m8n8.x4.shared.b16 {%0,%1,%2,%3}, [%4];"
                 : "=r"(r[0]), "=r"(r[1]), "=r"(r[2]), "=r"(r[3]) : "r"(a));
}
__device__ __forceinline__ void mma16816(float* c, const uint32_t* a, const uint32_t* b) {
    asm volatile("mma.sync.aligned.m16n8k16.row.col.f32.bf16.bf16.f32 "
                 "{%0,%1,%2,%3}, {%4,%5,%6,%7}, {%8,%9}, {%0,%1,%2,%3};"
                 : "+f"(c[0]), "+f"(c[1]), "+f"(c[2]), "+f"(c[3])
                 : "r"(a[0]), "r"(a[1]), "r"(a[2]), "r"(a[3]), "r"(b[0]), "r"(b[1]));
}
__device__ __forceinline__ void mma16816h(float* c, const uint32_t* a, const uint32_t* b) {
    asm volatile("mma.sync.aligned.m16n8k16.row.col.f32.f16.f16.f32 "
                 "{%0,%1,%2,%3}, {%4,%5,%6,%7}, {%8,%9}, {%0,%1,%2,%3};"
                 : "+f"(c[0]), "+f"(c[1]), "+f"(c[2]), "+f"(c[3])
                 : "r"(a[0]), "r"(a[1]), "r"(a[2]), "r"(a[3]), "r"(b[0]), "r"(b[1]));
}

// ---------------------------------------------------------------------------
// Static scratch (allocation-free rule)
// ---------------------------------------------------------------------------
__device__ __align__(256) __nv_bfloat16 g_xh[MS*DD], g_xl[MS*DD];
__device__ __align__(256) __nv_bfloat16 g_wth[3*DD*DD], g_wtl[3*DD*DD];   // W^T concat [3N,K]
__device__ __align__(256) __nv_bfloat16 g_qh[MS*DD], g_ql[MS*DD];
__device__ __align__(256) __nv_bfloat16 g_kh[MS*DD], g_kl[MS*DD];
__device__ __align__(256) __half         g_v16[MS*DD];
__device__ __align__(256) __half         g_vt16[(size_t)BB*DD*SS];
__device__ __align__(256) float          g_p[(size_t)BB*SS*SS];
__device__ __align__(256) __half         g_p16[(size_t)BB*SS*SS];
__device__ __align__(256) float          g_ent[MS];

// Epilogue routing for the fused QKV projection: q,k -> bf16 hi/lo; v -> fp16
struct ProjOut {
    const float* bias[3];
    __nv_bfloat16* oh[2];
    __nv_bfloat16* ol[2];
    __half* o16;
};

// ---------------------------------------------------------------------------
// bf16 split GEMM via mma.sync, PERSISTENT tiles:
//   C[M,N] = (Ah+Al)[M,K] x (Bh+Bl)[N,K]^T   (3 MMAs: hh + hl + lh)
// CTA tile 128x128, K-chunk 32, 256 threads = 8 warps (4 M x 2 N),
// 3-stage cp.async ring, ONE barrier/chunk, 2 CTAs/SM, grid = NPERS.
// ---------------------------------------------------------------------------
template<int EPI>
__global__ __launch_bounds__(256, 2)
void mma_gemm(const __nv_bfloat16* __restrict__ Ah, const __nv_bfloat16* __restrict__ Al,
              const __nv_bfloat16* __restrict__ Bh, const __nv_bfloat16* __restrict__ Bl,
              float* __restrict__ Cf, ProjOut po,
              int N, int K, long sA, long sB, long sC,
              int tX, int tY, int nTiles)
{
    extern __shared__ char sm[];
    const uint32_t sb = smem_u32(sm);
    const int tid = threadIdx.x, lane = tid & 31, warp = tid >> 5;
    const int wm = warp & 3, wn = warp >> 2;     // 4 M-warps x 2 N-warps
    const int NC = K >> 5;

    for (int tile = blockIdx.x; tile < nTiles; tile += NPERS) {
        const int bx = tile % tX;
        const int by = (tile / tX) % tY;
        const int bz = tile / (tX * tY);

        const __nv_bfloat16* srcA[2] = {
            Ah + (long)bz * sA + (long)by * 128 * K,
            Al + (long)bz * sA + (long)by * 128 * K };
        const __nv_bfloat16* srcB[2] = {
            Bh + (long)bz * sB + (long)bx * 128 * K,
            Bl + (long)bz * sB + (long)bx * 128 * K };

        float acc[2][8][4];
        #pragma unroll
        for (int a = 0; a < 2; a++)
            #pragma unroll
            for (int b = 0; b < 8; b++)
                #pragma unroll
                for (int c = 0; c < 4; c++) acc[a][b][c] = 0.f;

        auto load_stage = [&](int c) {
            const uint32_t dstS = sb + (uint32_t)(c % NSTAGE) * STAGEB;
            const long kof = (long)c * 32;
            #pragma unroll
            for (int p = 0; p < 4; p++) {
                const int u = tid + p * 256;
                const int r = u >> 3, seg = u & 7;
                const int hl = seg >> 2;
                const long so = kof + (seg & 3) * 8;
                CP16(dstS + r * ROWB + seg * 16,          srcA[hl] + (long)r * K + so);
                CP16(dstS + ATILEB + r * ROWB + seg * 16, srcB[hl] + (long)r * K + so);
            }
            CPCOMMIT();
        };

        load_stage(0);
        if (NC > 1) load_stage(1);

        for (int c = 0; c < NC; c++) {
            if (c + 2 <= NC) { CPWAIT(1); } else { CPWAIT(0); }
            __syncthreads();
            if (c + 2 < NC) load_stage(c + 2);

            const uint32_t stb = sb + (uint32_t)(c % NSTAGE) * STAGEB;
            #pragma unroll
            for (int ks = 0; ks < 2; ks++) {
                uint32_t aHi[2][4], aLo[2][4];
                const int rA   = wm * 32 + (lane & 15);
                const int colA = ks * 32 + ((lane >> 4) << 4);
                #pragma unroll
                for (int mf = 0; mf < 2; mf++) {
                    const uint32_t ad = stb + (rA + mf * 16) * ROWB + colA;
                    ldsm4(aHi[mf], ad);
                    ldsm4(aLo[mf], ad + 64);
                }
                const int rB   = wn * 64 + ((lane >> 4) & 1) * 8 + (lane & 7);
                const int colB = ks * 32 + ((lane >> 3) & 1) * 16;
                #pragma unroll
                for (int g = 0; g < 4; g++) {
                    uint32_t bh4[4], bl4[4];
                    const uint32_t bd = stb + ATILEB + (rB + g * 16) * ROWB + colB;
                    ldsm4(bh4, bd);
                    ldsm4(bl4, bd + 64);
                    #pragma unroll
                    for (int mf = 0; mf < 2; mf++) {
                        mma16816(acc[mf][2*g],   aHi[mf], bh4);
                        mma16816(acc[mf][2*g],   aHi[mf], bl4);
                        mma16816(acc[mf][2*g],   aLo[mf], bh4);
                        mma16816(acc[mf][2*g+1], aHi[mf], bh4 + 2);
                        mma16816(acc[mf][2*g+1], aHi[mf], bl4 + 2);
                        mma16816(acc[mf][2*g+1], aLo[mf], bh4 + 2);
                    }
                }
            }
        }

        // ---- epilogue ----
        const long rbase = (long)by * 128 + wm * 32 + (lane >> 2);
        const int  gcol0 = bx * 128;

        if (EPI == 0) {
            #pragma unroll
            for (int mf = 0; mf < 2; mf++)
                #pragma unroll
                for (int rh = 0; rh < 2; rh++) {
                    const long r = rbase + mf * 16 + rh * 8;
                    #pragma unroll
                    for (int nf = 0; nf < 8; nf++) {
                        const int col = gcol0 + wn * 64 + 2 * (lane & 3) + nf * 8;
                        float2 f2;
                        f2.x = acc[mf][nf][rh * 2 + 0];
                        f2.y = acc[mf][nf][rh * 2 + 1];
                        *(float2*)(Cf + (long)bz * sC + r * N + col) = f2;
                    }
                }
        } else {
            const int which = gcol0 >> 10;           // 0=q, 1=k, 2=v
            const int lcol0 = gcol0 & 1023;
            const float* bias = po.bias[which];
            if (which < 2) {
                __nv_bfloat16* Oh = po.oh[which];
                __nv_bfloat16* Ol = po.ol[which];
                #pragma unroll
                for (int mf = 0; mf < 2; mf++)
                    #pragma unroll
                    for (int rh = 0; rh < 2; rh++) {
                        const long r = rbase + mf * 16 + rh * 8;
                        #pragma unroll
                        for (int nf = 0; nf < 8; nf++) {
                            const int col = lcol0 + wn * 64 + 2 * (lane & 3) + nf * 8;
                            float v0 = acc[mf][nf][rh * 2 + 0] + bias[col];
                            float v1 = acc[mf][nf][rh * 2 + 1] + bias[col + 1];
                            __nv_bfloat16 h0 = __float2bfloat16(v0);
                            __nv_bfloat16 h1 = __float2bfloat16(v1);
                            __nv_bfloat162 hh; hh.x = h0; hh.y = h1;
                            __nv_bfloat162 ll;
                            ll.x = __float2bfloat16(v0 - __bfloat162float(h0));
                            ll.y = __float2bfloat16(v1 - __bfloat162float(h1));
                            *(__nv_bfloat162*)(Oh + r * DD + col) = hh;
                            *(__nv_bfloat162*)(Ol + r * DD + col) = ll;
                        }
                    }
            } else {
                __half* O = po.o16;
                #pragma unroll
                for (int mf = 0; mf < 2; mf++)
                    #pragma unroll
                    for (int rh = 0; rh < 2; rh++) {
                        const long r = rbase + mf * 16 + rh * 8;
                        #pragma unroll
                        for (int nf = 0; nf < 8; nf++) {
                            const int col = lcol0 + wn * 64 + 2 * (lane & 3) + nf * 8;
                            float v0 = acc[mf][nf][rh * 2 + 0] + bias[col];
                            float v1 = acc[mf][nf][rh * 2 + 1] + bias[col + 1];
                            __half2 hv; hv.x = __float2half(v0); hv.y = __float2half(v1);
                            *(__half2*)(O + r * DD + col) = hv;
                        }
                    }
            }
        }
        __syncthreads();   // protect smem ring before next tile's prologue
    }
}

// ---------------------------------------------------------------------------
// fp16 single-term GEMM, persistent tiles. Used for PV.
// ---------------------------------------------------------------------------
__global__ __launch_bounds__(256, 2)
void mma_gemm_h1(const __half* __restrict__ A, const __half* __restrict__ B,
                 float* __restrict__ Cf, int N, int K, long sA, long sB, long sC,
                 int tX, int tY, int nTiles)
{
    extern __shared__ char sm[];
    const uint32_t sb = smem_u32(sm);
    const int tid = threadIdx.x, lane = tid & 31, warp = tid >> 5;
    const int wm = warp & 3, wn = warp >> 2;
    const int NC = K >> 5;

    for (int tile = blockIdx.x; tile < nTiles; tile += NPERS) {
        const int bx = tile % tX;
        const int by = (tile / tX) % tY;
        const int bz = tile / (tX * tY);

        const __half* srcA = A + (long)bz * sA + (long)by * 128 * K;
        const __half* srcB = B + (long)bz * sB + (long)bx * 128 * K;

        float acc[2][8][4];
        #pragma unroll
        for (int a = 0; a < 2; a++)
            #pragma unroll
            for (int b = 0; b < 8; b++)
                #pragma unroll
                for (int c = 0; c < 4; c++) acc[a][b][c] = 0.f;

        auto load_stage = [&](int c) {
            const uint32_t dstS = sb + (uint32_t)(c % NSTAGE) * STAGE2;
            const long kof = (long)c * 32;
            #pragma unroll
            for (int p = 0; p < 2; p++) {
                const int u = tid + p * 256;
                const int r = u >> 2, s = u & 3;
                const long so = kof + s * 8;
                CP16(dstS + r * ROWB2 + s * 16,         srcA + (long)r * K + so);
                CP16(dstS + ATIL2 + r * ROWB2 + s * 16, srcB + (long)r * K + so);
            }
            CPCOMMIT();
        };

        load_stage(0);
        if (NC > 1) load_stage(1);

        for (int c = 0; c < NC; c++) {
            if (c + 2 <= NC) { CPWAIT(1); } else { CPWAIT(0); }
            __syncthreads();
            if (c + 2 < NC) load_stage(c + 2);

            const uint32_t stb = sb + (uint32_t)(c % NSTAGE) * STAGE2;
            #pragma unroll
            for (int ks = 0; ks < 2; ks++) {
                uint32_t aF[2][4];
                const int rA   = wm * 32 + (lane & 15);
                const int colA = ks * 32 + ((lane >> 4) << 4);
                #pragma unroll
                for (int mf = 0; mf < 2; mf++)
                    ldsm4(aF[mf], stb + (rA + mf * 16) * ROWB2 + colA);
                const int rB   = wn * 64 + ((lane >> 4) & 1) * 8 + (lane & 7);
                const int colB = ks * 32 + ((lane >> 3) & 1) * 16;
                #pragma unroll
                for (int g = 0; g < 4; g++) {
                    uint32_t b4[4];
                    ldsm4(b4, stb + ATIL2 + (rB + g * 16) * ROWB2 + colB);
                    #pragma unroll
                    for (int mf = 0; mf < 2; mf++) {
                        mma16816h(acc[mf][2*g],   aF[mf], b4);
                        mma16816h(acc[mf][2*g+1], aF[mf], b4 + 2);
                    }
                }
            }
        }

        const long rbase = (long)by * 128 + wm * 32 + (lane >> 2);
        const int  gcol0 = bx * 128;
        #pragma unroll
        for (int mf = 0; mf < 2; mf++)
            #pragma unroll
            for (int rh = 0; rh < 2; rh++) {
                const long r = rbase + mf * 16 + rh * 8;
                #pragma unroll
                for (int nf = 0; nf < 8; nf++) {
                    const int col = gcol0 + wn * 64 + 2 * (lane & 3) + nf * 8;
                    float2 f2;
                    f2.x = acc[mf][nf][rh * 2 + 0];
                    f2.y = acc[mf][nf][rh * 2 + 1];
                    *(float2*)(Cf + (long)bz * sC + r * N + col) = f2;
                }
            }
        __syncthreads();
    }
}

// ---------------------------------------------------------------------------
// fp32 -> bf16 hi/lo elementwise split (float4 vectorized)
// ---------------------------------------------------------------------------
__global__ void split_kernel(const float* __restrict__ in, __nv_bfloat16* __restrict__ oh,
                             __nv_bfloat16* __restrict__ ol, int n4)
{
    int i = blockIdx.x * 256 + threadIdx.x;
    if (i < n4) {
        float4 v = ((const float4*)in)[i];
        __nv_bfloat16 h0 = __float2bfloat16(v.x), h1 = __float2bfloat16(v.y);
        __nv_bfloat16 h2 = __float2bfloat16(v.z), h3 = __float2bfloat16(v.w);
        __nv_bfloat162 hA; hA.x = h0; hA.y = h1;
        __nv_bfloat162 hB; hB.x = h2; hB.y = h3;
        __nv_bfloat162 lA, lB;
        lA.x = __float2bfloat16(v.x - __bfloat162float(h0));
        lA.y = __float2bfloat16(v.y - __bfloat162float(h1));
        lB.x = __float2bfloat16(v.z - __bfloat162float(h2));
        lB.y = __float2bfloat16(v.w - __bfloat162float(h3));
        ((__nv_bfloat162*)oh)[2*i]   = hA;
        ((__nv_bfloat162*)oh)[2*i+1] = hB;
        ((__nv_bfloat162*)ol)[2*i]   = lA;
        ((__nv_bfloat162*)ol)[2*i+1] = lB;
    }
}

// ---------------------------------------------------------------------------
// Transpose + split fp32 [R,C] -> bf16 hi/lo [C,R] (weights)
// ---------------------------------------------------------------------------
__global__ void transpose_split(const float* __restrict__ in, __nv_bfloat16* __restrict__ oh,
                                __nv_bfloat16* __restrict__ ol, int R, int C)
{
    __shared__ float t[32][33];
    const int c0 = blockIdx.x * 32, rr0 = blockIdx.y * 32;
    const int tx = threadIdx.x, ty = threadIdx.y;
    #pragma unroll
    for (int k = 0; k < 32; k += 8)
        t[ty + k][tx] = in[(long)(rr0 + ty + k) * C + c0 + tx];
    __syncthreads();
    #pragma unroll
    for (int k = 0; k < 32; k += 8) {
        float v = t[tx][ty + k];
        __nv_bfloat16 h = __float2bfloat16(v);
        long o = (long)(c0 + ty + k) * R + rr0 + tx;
        oh[o] = h;
        ol[o] = __float2bfloat16(v - __bfloat162float(h));
    }
}

// ---------------------------------------------------------------------------
// Batched fp16 transpose: [R,C] -> [C,R]  (v -> v^T)
// ---------------------------------------------------------------------------
__global__ void transpose_h(const __half* __restrict__ in, __half* __restrict__ out,
                            int R, int C, long sIn, long sOut)
{
    __shared__ __half t[32][34];
    in  += (long)blockIdx.z * sIn;
    out += (long)blockIdx.z * sOut;
    const int c0 = blockIdx.x * 32, rr0 = blockIdx.y * 32;
    const int tx = threadIdx.x, ty = threadIdx.y;
    #pragma unroll
    for (int k = 0; k < 32; k += 8)
        t[ty + k][tx] = in[(long)(rr0 + ty + k) * C + c0 + tx];
    __syncthreads();
    #pragma unroll
    for (int k = 0; k < 32; k += 8)
        out[(long)(c0 + ty + k) * R + rr0 + tx] = t[tx][ty + k];
}

// ---------------------------------------------------------------------------
// Row softmax + entropy; writes probs as fp16 (PV GEMM A operand)
// ---------------------------------------------------------------------------
__global__ void softmax_ent(const float* __restrict__ P, __half* __restrict__ P16,
                            float* __restrict__ ent, const float* __restrict__ temp)
{
    __shared__ float red[256];
    const float* p = P + (long)blockIdx.x * SS;
    __half* o = P16 + (long)blockIdx.x * SS;
    const int tid = threadIdx.x;
    const float scale = 1.0f / (8.0f * temp[0]);

    float v[8];
    #pragma unroll
    for (int j = 0; j < 8; j++) v[j] = p[tid + j * 256] * scale;

    float m = v[0];
    #pragma unroll
    for (int j = 1; j < 8; j++) m = fmaxf(m, v[j]);
    red[tid] = m; __syncthreads();
    #pragma unroll
    for (int s = 128; s > 0; s >>= 1) {
        if (tid < s) red[tid] = fmaxf(red[tid], red[tid + s]);
        __syncthreads();
    }
    m = red[0]; __syncthreads();

    float e[8], l = 0.f, t = 0.f;
    #pragma unroll
    for (int j = 0; j < 8; j++) {
        e[j] = __expf(v[j] - m);
        l += e[j];
        t += e[j] * v[j];
    }
    red[tid] = l; __syncthreads();
    #pragma unroll
    for (int s = 128; s > 0; s >>= 1) {
        if (tid < s) red[tid] += red[tid + s];
        __syncthreads();
    }
    l = red[0]; __syncthreads();
    red[tid] = t; __syncthreads();
    #pragma unroll
    for (int s = 128; s > 0; s >>= 1) {
        if (tid < s) red[tid] += red[tid + s];
        __syncthreads();
    }
    t = red[0]; __syncthreads();

    const float inv = 1.0f / l;
    #pragma unroll
    for (int j = 0; j < 8; j++)
        o[tid + j * 256] = __float2half(e[j] * inv);

    if (tid == 0) ent[blockIdx.x] = m + logf(l) - t * inv;
}

__global__ void ent_reduce(const float* __restrict__ ent, float* __restrict__ out)
{
    __shared__ float red[256];
    const int tid = threadIdx.x;
    float s = 0.f;
    for (int i = tid; i < MS; i += 256) s += ent[i];
    red[tid] = s; __syncthreads();
    #pragma unroll
    for (int k = 128; k > 0; k >>= 1) {
        if (tid < k) red[tid] += red[tid + k];
        __syncthreads();
    }
    if (tid == 0) out[0] = red[0] / (float)MS;
}

// ---------------------------------------------------------------------------
extern "C" void kernel_launch(void* const* d_in, const int* in_sizes, int n_in,
                              void* d_out, int out_size)
{
    const float* x    = (const float*)d_in[0];
    const float* Wq   = (const float*)d_in[1];
    const float* bq   = (const float*)d_in[2];
    const float* Wk   = (const float*)d_in[3];
    const float* bk   = (const float*)d_in[4];
    const float* Wv   = (const float*)d_in[5];
    const float* bv   = (const float*)d_in[6];
    const float* temp = (const float*)d_in[7];
    float* out = (float*)d_out;

    __nv_bfloat16 *xh, *xl, *wth, *wtl, *qh, *ql, *kh, *kl;
    __half *v16, *vt16, *p16;
    float *p, *ent;
    cudaGetSymbolAddress((void**)&xh,  g_xh);  cudaGetSymbolAddress((void**)&xl,  g_xl);
    cudaGetSymbolAddress((void**)&wth, g_wth); cudaGetSymbolAddress((void**)&wtl, g_wtl);
    cudaGetSymbolAddress((void**)&qh,  g_qh);  cudaGetSymbolAddress((void**)&ql,  g_ql);
    cudaGetSymbolAddress((void**)&kh,  g_kh);  cudaGetSymbolAddress((void**)&kl,  g_kl);
    cudaGetSymbolAddress((void**)&v16, g_v16); cudaGetSymbolAddress((void**)&vt16, g_vt16);
    cudaGetSymbolAddress((void**)&p,   g_p);   cudaGetSymbolAddress((void**)&p16, g_p16);
    cudaGetSymbolAddress((void**)&ent, g_ent);

    cudaFuncSetAttribute(mma_gemm<0>, cudaFuncAttributeMaxDynamicSharedMemorySize, SMEMB);
    cudaFuncSetAttribute(mma_gemm<1>, cudaFuncAttributeMaxDynamicSharedMemorySize, SMEMB);
    cudaFuncSetAttribute(mma_gemm_h1, cudaFuncAttributeMaxDynamicSharedMemorySize, SMEM2);

    ProjOut poNull = {};

    // 1) Split x; transpose+split weights into concat W^T [3*D, D]
    split_kernel<<<(MS*DD/4 + 255) / 256, 256>>>(x, xh, xl, MS*DD/4);
    {
        dim3 blk(32, 8);
        dim3 grd(DD / 32, DD / 32, 1);
        transpose_split<<<grd, blk>>>(Wq, wth + 0*DD*DD, wtl + 0*DD*DD, DD, DD);
        transpose_split<<<grd, blk>>>(Wk, wth + 1*DD*DD, wtl + 1*DD*DD, DD, DD);
        transpose_split<<<grd, blk>>>(Wv, wth + 2*DD*DD, wtl + 2*DD*DD, DD, DD);
    }
    // 2) Fused QKV projection (persistent): q,k -> bf16 hi/lo; v -> fp16
    {
        ProjOut po;
        po.bias[0] = bq; po.bias[1] = bk; po.bias[2] = bv;
        po.oh[0] = qh; po.oh[1] = kh;
        po.ol[0] = ql; po.ol[1] = kl;
        po.o16 = v16;
        const int tX = 3*DD/128, tY = MS/128;            // 24 x 64 = 1536 tiles
        mma_gemm<1><<<NPERS, 256, SMEMB>>>(xh, xl, wth, wtl, nullptr, po,
                                           3*DD, DD, 0, 0, 0, tX, tY, tX*tY);
    }
    // 3) v -> v^T fp16 per batch ([S,D] -> [D,S])
    {
        dim3 blk(32, 8);
        dim3 grd(DD / 32, SS / 32, BB);
        transpose_h<<<grd, blk>>>(v16, vt16, SS, DD, (long)SS * DD, (long)DD * SS);
    }
    // 4) Scores (persistent; per batch 2048x2048, K=1024), bf16 3-term
    {
        const int tX = SS/128, tY = SS/128;              // 16 x 16 x 4 = 1024 tiles
        mma_gemm<0><<<NPERS, 256, SMEMB>>>(qh, ql, kh, kl, p, poNull,
                                           SS, DD, (long)SS*DD, (long)SS*DD, (long)SS*SS,
                                           tX, tY, tX*tY*BB);
    }
    // 5) Softmax + entropy; probs -> fp16
    softmax_ent<<<MS, 256>>>(p, p16, ent, temp);
    // 6) PV (persistent; per batch 2048x1024, K=2048), single fp16 MMA
    {
        const int tX = DD/128, tY = SS/128;              // 8 x 16 x 4 = 512 tiles
        mma_gemm_h1<<<NPERS, 256, SMEM2>>>(p16, vt16, out,
                                           DD, SS, (long)SS*SS, (long)DD*SS, (long)SS*DD,
                                           tX, tY, tX*tY*BB);
    }
    // 7) Entropy mean scalar
    ent_reduce<<<1, 256>>>(ent, out + OUT_ELEMS);
}

// round 10
// speedup vs baseline: 1.2817x; 1.2817x over previous
#include <cuda_runtime.h>
#include <cuda_bf16.h>
#include <cuda_fp16.h>
#include <math.h>
#include <stdint.h>

// Problem dims (fixed)
#define BB 4
#define SS 2048
#define DD 1024
#define MS (BB*SS)          // 8192 rows total
#define OUT_ELEMS (MS*DD)

// --- bf16 split GEMM smem geometry: rows hold hi(64B)|lo(64B), stride 144B ---
#define ROWB   144
#define ATILEB (128*ROWB)
#define STAGEB (2*ATILEB)              // A + B tile = 36864 B
#define NSTAGE 3
#define SMEMB  (NSTAGE*STAGEB)         // 110592 B -> 2 CTAs/SM

// --- fp16 single GEMM smem geometry: rows 64B data + 16B pad -> 80B ---
#define ROWB2   80
#define ATIL2   (128*ROWB2)
#define STAGE2  (2*ATIL2)              // 20480 B
#define SMEM2   (NSTAGE*STAGE2)        // 61440 B

// ---------------------------------------------------------------------------
// PTX helpers (sm_80-level only: cp.async, ldmatrix, mma.sync)
// ---------------------------------------------------------------------------
__device__ __forceinline__ uint32_t smem_u32(const void* p) {
    uint32_t a;
    asm("{ .reg .u64 t; cvta.to.shared.u64 t, %1; cvt.u32.u64 %0, t; }" : "=r"(a) : "l"(p));
    return a;
}
#define CP16(d, s) asm volatile("cp.async.cg.shared.global [%0], [%1], 16;" :: "r"(d), "l"(s))
#define CPCOMMIT() asm volatile("cp.async.commit_group;" ::: "memory")
#define CPWAIT(n)  asm volatile("cp.async.wait_group %0;" :: "n"(n) : "memory")

__device__ __forceinline__ void ldsm4(uint32_t* r, uint32_t a) {
    asm volatile("ldmatrix.sync.aligned.m8n8.x4.shared.b16 {%0,%1,%2,%3}, [%4];"
                 : "=r"(r[0]), "=r"(r[1]), "=r"(r[2]), "=r"(r[3]) : "r"(a));
}
__device__ __forceinline__ void mma16816(float* c, const uint32_t* a, const uint32_t* b) {
    asm volatile("mma.sync.aligned.m16n8k16.row.col.f32.bf16.bf16.f32 "
                 "{%0,%1,%2,%3}, {%4,%5,%6,%7}, {%8,%9}, {%0,%1,%2,%3};"
                 : "+f"(c[0]), "+f"(c[1]), "+f"(c[2]), "+f"(c[3])
                 : "r"(a[0]), "r"(a[1]), "r"(a[2]), "r"(a[3]), "r"(b[0]), "r"(b[1]));
}
__device__ __forceinline__ void mma16816h(float* c, const uint32_t* a, const uint32_t* b) {
    asm volatile("mma.sync.aligned.m16n8k16.row.col.f32.f16.f16.f32 "
                 "{%0,%1,%2,%3}, {%4,%5,%6,%7}, {%8,%9}, {%0,%1,%2,%3};"
                 : "+f"(c[0]), "+f"(c[1]), "+f"(c[2]), "+f"(c[3])
                 : "r"(a[0]), "r"(a[1]), "r"(a[2]), "r"(a[3]), "r"(b[0]), "r"(b[1]));
}

// ---------------------------------------------------------------------------
// Static scratch (allocation-free rule)
// ---------------------------------------------------------------------------
__device__ __align__(256) __nv_bfloat16 g_xh[MS*DD], g_xl[MS*DD];
__device__ __align__(256) __half         g_x16[MS*DD];
__device__ __align__(256) __half         g_xt16[MS*DD];                 // per-batch x^T
__device__ __align__(256) __nv_bfloat16 g_wqh[DD*DD], g_wql[DD*DD];
__device__ __align__(256) __nv_bfloat16 g_wkh[DD*DD], g_wkl[DD*DD];
__device__ __align__(256) __half         g_wvt16[DD*DD];                 // Wv^T fp16
__device__ __align__(256) float          g_mtp[4*DD*DD];                 // M^T K-split partials
__device__ __align__(256) __nv_bfloat16 g_mth[DD*DD], g_mtl[DD*DD];     // M^T = Wk Wq^T
__device__ __align__(256) __nv_bfloat16 g_yh[MS*DD], g_yl[MS*DD];       // y = x M
__device__ __align__(256) float          g_p[(size_t)BB*SS*SS];
__device__ __align__(256) __half         g_p16[(size_t)BB*SS*SS];
__device__ __align__(256) __half         g_z16[MS*DD];                   // z = p x
__device__ __align__(256) float          g_cq[DD], g_ck[DD], g_u[MS], g_w[MS], g_s0[1];
__device__ __align__(256) float          g_ent[MS];

// ---------------------------------------------------------------------------
// bf16 split GEMM via mma.sync:
//   C[M,N] = (Ah+Al)[.,K] x (Bh+Bl)[.,K]^T   (3 MMAs: hh + hl + lh)
// CTA tile 128x128, K-chunk 32, 256 threads = 8 warps (4 M x 2 N),
// 3-stage cp.async ring, ONE barrier/chunk, 2 CTAs/SM.
// EPI 0: fp32 store.  EPI 2: bf16 hi/lo split store (Oh/Ol, row stride N).
// lda/ldb = row strides (elements); K = contraction length.
// ---------------------------------------------------------------------------
template<int EPI>
__global__ __launch_bounds__(256, 2)
void mma_gemm(const __nv_bfloat16* __restrict__ Ah, const __nv_bfloat16* __restrict__ Al,
              const __nv_bfloat16* __restrict__ Bh, const __nv_bfloat16* __restrict__ Bl,
              float* __restrict__ Cf, __nv_bfloat16* __restrict__ Oh, __nv_bfloat16* __restrict__ Ol,
              int N, int K, int lda, int ldb, long sA, long sB, long sC)
{
    extern __shared__ char sm[];
    const uint32_t sb = smem_u32(sm);
    const int tid = threadIdx.x, lane = tid & 31, warp = tid >> 5;
    const int wm = warp & 3, wn = warp >> 2;     // 4 M-warps x 2 N-warps
    const int bz = blockIdx.z;

    const __nv_bfloat16* srcA[2] = {
        Ah + (long)bz * sA + (long)blockIdx.y * 128 * lda,
        Al + (long)bz * sA + (long)blockIdx.y * 128 * lda };
    const __nv_bfloat16* srcB[2] = {
        Bh + (long)bz * sB + (long)blockIdx.x * 128 * ldb,
        Bl + (long)bz * sB + (long)blockIdx.x * 128 * ldb };

    float acc[2][8][4];
    #pragma unroll
    for (int a = 0; a < 2; a++)
        #pragma unroll
        for (int b = 0; b < 8; b++)
            #pragma unroll
            for (int c = 0; c < 4; c++) acc[a][b][c] = 0.f;

    const int NC = K >> 5;

    auto load_stage = [&](int c) {
        const uint32_t dstS = sb + (uint32_t)(c % NSTAGE) * STAGEB;
        const long kof = (long)c * 32;
        #pragma unroll
        for (int p = 0; p < 4; p++) {
            const int u = tid + p * 256;
            const int r = u >> 3, seg = u & 7;
            const int hl = seg >> 2;
            const long so = kof + (seg & 3) * 8;
            CP16(dstS + r * ROWB + seg * 16,          srcA[hl] + (long)r * lda + so);
            CP16(dstS + ATILEB + r * ROWB + seg * 16, srcB[hl] + (long)r * ldb + so);
        }
        CPCOMMIT();
    };

    load_stage(0);
    if (NC > 1) load_stage(1);

    for (int c = 0; c < NC; c++) {
        if (c + 2 <= NC) { CPWAIT(1); } else { CPWAIT(0); }
        __syncthreads();
        if (c + 2 < NC) load_stage(c + 2);

        const uint32_t stb = sb + (uint32_t)(c % NSTAGE) * STAGEB;
        #pragma unroll
        for (int ks = 0; ks < 2; ks++) {
            uint32_t aHi[2][4], aLo[2][4];
            const int rA   = wm * 32 + (lane & 15);
            const int colA = ks * 32 + ((lane >> 4) << 4);
            #pragma unroll
            for (int mf = 0; mf < 2; mf++) {
                const uint32_t ad = stb + (rA + mf * 16) * ROWB + colA;
                ldsm4(aHi[mf], ad);
                ldsm4(aLo[mf], ad + 64);
            }
            const int rB   = wn * 64 + ((lane >> 4) & 1) * 8 + (lane & 7);
            const int colB = ks * 32 + ((lane >> 3) & 1) * 16;
            #pragma unroll
            for (int g = 0; g < 4; g++) {
                uint32_t bh4[4], bl4[4];
                const uint32_t bd = stb + ATILEB + (rB + g * 16) * ROWB + colB;
                ldsm4(bh4, bd);
                ldsm4(bl4, bd + 64);
                #pragma unroll
                for (int mf = 0; mf < 2; mf++) {
                    mma16816(acc[mf][2*g],   aHi[mf], bh4);
                    mma16816(acc[mf][2*g],   aHi[mf], bl4);
                    mma16816(acc[mf][2*g],   aLo[mf], bh4);
                    mma16816(acc[mf][2*g+1], aHi[mf], bh4 + 2);
                    mma16816(acc[mf][2*g+1], aHi[mf], bl4 + 2);
                    mma16816(acc[mf][2*g+1], aLo[mf], bh4 + 2);
                }
            }
        }
    }

    // ---- epilogue ----
    const long rbase = (long)blockIdx.y * 128 + wm * 32 + (lane >> 2);
    const int  gcol0 = blockIdx.x * 128;

    #pragma unroll
    for (int mf = 0; mf < 2; mf++)
        #pragma unroll
        for (int rh = 0; rh < 2; rh++) {
            const long r = rbase + mf * 16 + rh * 8;
            #pragma unroll
            for (int nf = 0; nf < 8; nf++) {
                const int col = gcol0 + wn * 64 + 2 * (lane & 3) + nf * 8;
                float v0 = acc[mf][nf][rh * 2 + 0];
                float v1 = acc[mf][nf][rh * 2 + 1];
                if (EPI == 0) {
                    float2 f2; f2.x = v0; f2.y = v1;
                    *(float2*)(Cf + (long)bz * sC + r * N + col) = f2;
                } else {
                    __nv_bfloat16 h0 = __float2bfloat16(v0);
                    __nv_bfloat16 h1 = __float2bfloat16(v1);
                    __nv_bfloat162 hh; hh.x = h0; hh.y = h1;
                    __nv_bfloat162 ll;
                    ll.x = __float2bfloat16(v0 - __bfloat162float(h0));
                    ll.y = __float2bfloat16(v1 - __bfloat162float(h1));
                    *(__nv_bfloat162*)(Oh + (long)bz * sC + r * N + col) = hh;
                    *(__nv_bfloat162*)(Ol + (long)bz * sC + r * N + col) = ll;
                }
            }
        }
}

// ---------------------------------------------------------------------------
// fp16 single-term GEMM: C[M,N] = A[.,K] x B[.,K]^T, fp32 accum.
// EPI 0: fp32 store + bias.  EPI 1: fp16 store.
// ---------------------------------------------------------------------------
template<int EPI>
__global__ __launch_bounds__(256, 2)
void mma_gemm_h1(const __half* __restrict__ A, const __half* __restrict__ B,
                 float* __restrict__ Cf, __half* __restrict__ Oz,
                 const float* __restrict__ bias,
                 int N, int K, int lda, int ldb, long sA, long sB, long sC)
{
    extern __shared__ char sm[];
    const uint32_t sb = smem_u32(sm);
    const int tid = threadIdx.x, lane = tid & 31, warp = tid >> 5;
    const int wm = warp & 3, wn = warp >> 2;
    const int bz = blockIdx.z;

    const __half* srcA = A + (long)bz * sA + (long)blockIdx.y * 128 * lda;
    const __half* srcB = B + (long)bz * sB + (long)blockIdx.x * 128 * ldb;

    float acc[2][8][4];
    #pragma unroll
    for (int a = 0; a < 2; a++)
        #pragma unroll
        for (int b = 0; b < 8; b++)
            #pragma unroll
            for (int c = 0; c < 4; c++) acc[a][b][c] = 0.f;

    const int NC = K >> 5;

    auto load_stage = [&](int c) {
        const uint32_t dstS = sb + (uint32_t)(c % NSTAGE) * STAGE2;
        const long kof = (long)c * 32;
        #pragma unroll
        for (int p = 0; p < 2; p++) {
            const int u = tid + p * 256;
            const int r = u >> 2, s = u & 3;
            const long so = kof + s * 8;
            CP16(dstS + r * ROWB2 + s * 16,         srcA + (long)r * lda + so);
            CP16(dstS + ATIL2 + r * ROWB2 + s * 16, srcB + (long)r * ldb + so);
        }
        CPCOMMIT();
    };

    load_stage(0);
    if (NC > 1) load_stage(1);

    for (int c = 0; c < NC; c++) {
        if (c + 2 <= NC) { CPWAIT(1); } else { CPWAIT(0); }
        __syncthreads();
        if (c + 2 < NC) load_stage(c + 2);

        const uint32_t stb = sb + (uint32_t)(c % NSTAGE) * STAGE2;
        #pragma unroll
        for (int ks = 0; ks < 2; ks++) {
            uint32_t aF[2][4];
            const int rA   = wm * 32 + (lane & 15);
            const int colA = ks * 32 + ((lane >> 4) << 4);
            #pragma unroll
            for (int mf = 0; mf < 2; mf++)
                ldsm4(aF[mf], stb + (rA + mf * 16) * ROWB2 + colA);
            const int rB   = wn * 64 + ((lane >> 4) & 1) * 8 + (lane & 7);
            const int colB = ks * 32 + ((lane >> 3) & 1) * 16;
            #pragma unroll
            for (int g = 0; g < 4; g++) {
                uint32_t b4[4];
                ldsm4(b4, stb + ATIL2 + (rB + g * 16) * ROWB2 + colB);
                #pragma unroll
                for (int mf = 0; mf < 2; mf++) {
                    mma16816h(acc[mf][2*g],   aF[mf], b4);
                    mma16816h(acc[mf][2*g+1], aF[mf], b4 + 2);
                }
            }
        }
    }

    const long rbase = (long)blockIdx.y * 128 + wm * 32 + (lane >> 2);
    const int  gcol0 = blockIdx.x * 128;
    #pragma unroll
    for (int mf = 0; mf < 2; mf++)
        #pragma unroll
        for (int rh = 0; rh < 2; rh++) {
            const long r = rbase + mf * 16 + rh * 8;
            #pragma unroll
            for (int nf = 0; nf < 8; nf++) {
                const int col = gcol0 + wn * 64 + 2 * (lane & 3) + nf * 8;
                float v0 = acc[mf][nf][rh * 2 + 0];
                float v1 = acc[mf][nf][rh * 2 + 1];
                if (EPI == 0) {
                    if (bias) { v0 += bias[col]; v1 += bias[col + 1]; }
                    float2 f2; f2.x = v0; f2.y = v1;
                    *(float2*)(Cf + (long)bz * sC + r * N + col) = f2;
                } else {
                    __half2 hv; hv.x = __float2half(v0); hv.y = __float2half(v1);
                    *(__half2*)(Oz + (long)bz * sC + r * N + col) = hv;
                }
            }
        }
}

// ---------------------------------------------------------------------------
// x -> bf16 hi/lo + fp16 (float4 vectorized)
// ---------------------------------------------------------------------------
__global__ void split_x_kernel(const float* __restrict__ in, __nv_bfloat16* __restrict__ oh,
                               __nv_bfloat16* __restrict__ ol, __half* __restrict__ o16, int n4)
{
    int i = blockIdx.x * 256 + threadIdx.x;
    if (i < n4) {
        float4 v = ((const float4*)in)[i];
        __nv_bfloat16 h0 = __float2bfloat16(v.x), h1 = __float2bfloat16(v.y);
        __nv_bfloat16 h2 = __float2bfloat16(v.z), h3 = __float2bfloat16(v.w);
        __nv_bfloat162 hA; hA.x = h0; hA.y = h1;
        __nv_bfloat162 hB; hB.x = h2; hB.y = h3;
        __nv_bfloat162 lA, lB;
        lA.x = __float2bfloat16(v.x - __bfloat162float(h0));
        lA.y = __float2bfloat16(v.y - __bfloat162float(h1));
        lB.x = __float2bfloat16(v.z - __bfloat162float(h2));
        lB.y = __float2bfloat16(v.w - __bfloat162float(h3));
        ((__nv_bfloat162*)oh)[2*i]   = hA;
        ((__nv_bfloat162*)oh)[2*i+1] = hB;
        ((__nv_bfloat162*)ol)[2*i]   = lA;
        ((__nv_bfloat162*)ol)[2*i+1] = lB;
        __half2 a; a.x = __float2half(v.x); a.y = __float2half(v.y);
        __half2 b; b.x = __float2half(v.z); b.y = __float2half(v.w);
        ((__half2*)o16)[2*i]   = a;
        ((__half2*)o16)[2*i+1] = b;
    }
}

// plain elementwise fp32 -> bf16 hi/lo
__global__ void split_kernel(const float* __restrict__ in, __nv_bfloat16* __restrict__ oh,
                             __nv_bfloat16* __restrict__ ol, int n4)
{
    int i = blockIdx.x * 256 + threadIdx.x;
    if (i < n4) {
        float4 v = ((const float4*)in)[i];
        __nv_bfloat16 h0 = __float2bfloat16(v.x), h1 = __float2bfloat16(v.y);
        __nv_bfloat16 h2 = __float2bfloat16(v.z), h3 = __float2bfloat16(v.w);
        __nv_bfloat162 hA; hA.x = h0; hA.y = h1;
        __nv_bfloat162 hB; hB.x = h2; hB.y = h3;
        __nv_bfloat162 lA, lB;
        lA.x = __float2bfloat16(v.x - __bfloat162float(h0));
        lA.y = __float2bfloat16(v.y - __bfloat162float(h1));
        lB.x = __float2bfloat16(v.z - __bfloat162float(h2));
        lB.y = __float2bfloat16(v.w - __bfloat162float(h3));
        ((__nv_bfloat162*)oh)[2*i]   = hA;
        ((__nv_bfloat162*)oh)[2*i+1] = hB;
        ((__nv_bfloat162*)ol)[2*i]   = lA;
        ((__nv_bfloat162*)ol)[2*i+1] = lB;
    }
}

// MT partials (4) -> sum -> bf16 hi/lo
__global__ void mt_reduce_split(const float* __restrict__ parts, __nv_bfloat16* __restrict__ oh,
                                __nv_bfloat16* __restrict__ ol, int n4)
{
    int i = blockIdx.x * 256 + threadIdx.x;
    if (i < n4) {
        float4 s = ((const float4*)parts)[i];
        #pragma unroll
        for (int p = 1; p < 4; p++) {
            float4 t = ((const float4*)(parts + (size_t)p * DD * DD))[i];
            s.x += t.x; s.y += t.y; s.z += t.z; s.w += t.w;
        }
        __nv_bfloat16 h0 = __float2bfloat16(s.x), h1 = __float2bfloat16(s.y);
        __nv_bfloat16 h2 = __float2bfloat16(s.z), h3 = __float2bfloat16(s.w);
        __nv_bfloat162 hA; hA.x = h0; hA.y = h1;
        __nv_bfloat162 hB; hB.x = h2; hB.y = h3;
        __nv_bfloat162 lA, lB;
        lA.x = __float2bfloat16(s.x - __bfloat162float(h0));
        lA.y = __float2bfloat16(s.y - __bfloat162float(h1));
        lB.x = __float2bfloat16(s.z - __bfloat162float(h2));
        lB.y = __float2bfloat16(s.w - __bfloat162float(h3));
        ((__nv_bfloat162*)oh)[2*i]   = hA;
        ((__nv_bfloat162*)oh)[2*i+1] = hB;
        ((__nv_bfloat162*)ol)[2*i]   = lA;
        ((__nv_bfloat162*)ol)[2*i+1] = lB;
    }
}

// fp32 [R,C] -> fp16 [C,R] transpose (Wv -> Wv^T)
__global__ void transpose_f2h(const float* __restrict__ in, __half* __restrict__ out,
                              int R, int C)
{
    __shared__ float t[32][33];
    const int c0 = blockIdx.x * 32, rr0 = blockIdx.y * 32;
    const int tx = threadIdx.x, ty = threadIdx.y;
    #pragma unroll
    for (int k = 0; k < 32; k += 8)
        t[ty + k][tx] = in[(long)(rr0 + ty + k) * C + c0 + tx];
    __syncthreads();
    #pragma unroll
    for (int k = 0; k < 32; k += 8)
        out[(long)(c0 + ty + k) * R + rr0 + tx] = __float2half(t[tx][ty + k]);
}

// Batched fp16 transpose: [R,C] -> [C,R]  (x16 -> x^T per batch)
__global__ void transpose_h(const __half* __restrict__ in, __half* __restrict__ out,
                            int R, int C, long sIn, long sOut)
{
    __shared__ __half t[32][34];
    in  += (long)blockIdx.z * sIn;
    out += (long)blockIdx.z * sOut;
    const int c0 = blockIdx.x * 32, rr0 = blockIdx.y * 32;
    const int tx = threadIdx.x, ty = threadIdx.y;
    #pragma unroll
    for (int k = 0; k < 32; k += 8)
        t[ty + k][tx] = in[(long)(rr0 + ty + k) * C + c0 + tx];
    __syncthreads();
    #pragma unroll
    for (int k = 0; k < 32; k += 8)
        out[(long)(c0 + ty + k) * R + rr0 + tx] = t[tx][ty + k];
}

// s0 = bq . bk
__global__ void s0_kernel(const float* __restrict__ bq, const float* __restrict__ bk,
                          float* __restrict__ s0)
{
    __shared__ float red[256];
    const int tid = threadIdx.x;
    float s = 0.f;
    for (int i = tid; i < DD; i += 256) s += bq[i] * bk[i];
    red[tid] = s; __syncthreads();
    #pragma unroll
    for (int k = 128; k > 0; k >>= 1) {
        if (tid < k) red[tid] += red[tid + k];
        __syncthreads();
    }
    if (tid == 0) s0[0] = red[0];
}

// cq = Wq bk, ck = Wk bq (warp per output element)
__global__ void gemv_cqck(const float* __restrict__ Wq, const float* __restrict__ Wk,
                          const float* __restrict__ bq, const float* __restrict__ bk,
                          float* __restrict__ cq, float* __restrict__ ck)
{
    const int lane = threadIdx.x & 31, warp = threadIdx.x >> 5;
    const int d = blockIdx.x * 8 + warp;
    float a1 = 0.f, a2 = 0.f;
    for (int i = lane; i < DD; i += 32) {
        a1 += Wq[(long)d * DD + i] * bk[i];
        a2 += Wk[(long)d * DD + i] * bq[i];
    }
    #pragma unroll
    for (int o = 16; o > 0; o >>= 1) {
        a1 += __shfl_xor_sync(0xffffffff, a1, o);
        a2 += __shfl_xor_sync(0xffffffff, a2, o);
    }
    if (lane == 0) { cq[d] = a1; ck[d] = a2; }
}

// u = x cq, w = x ck (warp per row)
__global__ void gemv_uw(const float* __restrict__ x, const float* __restrict__ cq,
                        const float* __restrict__ ck, float* __restrict__ u, float* __restrict__ w)
{
    const int lane = threadIdx.x & 31, warp = threadIdx.x >> 5;
    const long r = (long)blockIdx.x * 8 + warp;
    float a1 = 0.f, a2 = 0.f;
    for (int d = lane; d < DD; d += 32) {
        float xv = x[r * DD + d];
        a1 += xv * cq[d];
        a2 += xv * ck[d];
    }
    #pragma unroll
    for (int o = 16; o > 0; o >>= 1) {
        a1 += __shfl_xor_sync(0xffffffff, a1, o);
        a2 += __shfl_xor_sync(0xffffffff, a2, o);
    }
    if (lane == 0) { u[r] = a1; w[r] = a2; }
}

// ---------------------------------------------------------------------------
// Row softmax + entropy; logits = (raw + u_r + w_c + s0)/(8*temp); probs fp16
// ---------------------------------------------------------------------------
__global__ void softmax_ent(const float* __restrict__ P, const float* __restrict__ u,
                            const float* __restrict__ w, const float* __restrict__ s0,
                            __half* __restrict__ P16, float* __restrict__ ent,
                            const float* __restrict__ temp)
{
    __shared__ float red[256];
    const float* p = P + (long)blockIdx.x * SS;
    __half* o = P16 + (long)blockIdx.x * SS;
    const int tid = threadIdx.x;
    const float scale = 1.0f / (8.0f * temp[0]);
    const float ub = u[blockIdx.x] + s0[0];
    const float* wb = w + (blockIdx.x / SS) * SS;

    float v[8];
    #pragma unroll
    for (int j = 0; j < 8; j++) {
        const int c = tid + j * 256;
        v[j] = (p[c] + ub + wb[c]) * scale;
    }

    float m = v[0];
    #pragma unroll
    for (int j = 1; j < 8; j++) m = fmaxf(m, v[j]);
    red[tid] = m; __syncthreads();
    #pragma unroll
    for (int s = 128; s > 0; s >>= 1) {
        if (tid < s) red[tid] = fmaxf(red[tid], red[tid + s]);
        __syncthreads();
    }
    m = red[0]; __syncthreads();

    float e[8], l = 0.f, t = 0.f;
    #pragma unroll
    for (int j = 0; j < 8; j++) {
        e[j] = __expf(v[j] - m);
        l += e[j];
        t += e[j] * v[j];
    }
    red[tid] = l; __syncthreads();
    #pragma unroll
    for (int s = 128; s > 0; s >>= 1) {
        if (tid < s) red[tid] += red[tid + s];
        __syncthreads();
    }
    l = red[0]; __syncthreads();
    red[tid] = t; __syncthreads();
    #pragma unroll
    for (int s = 128; s > 0; s >>= 1) {
        if (tid < s) red[tid] += red[tid + s];
        __syncthreads();
    }
    t = red[0]; __syncthreads();

    const float inv = 1.0f / l;
    #pragma unroll
    for (int j = 0; j < 8; j++)
        o[tid + j * 256] = __float2half(e[j] * inv);

    if (tid == 0) ent[blockIdx.x] = m + logf(l) - t * inv;
}

__global__ void ent_reduce(const float* __restrict__ ent, float* __restrict__ out)
{
    __shared__ float red[256];
    const int tid = threadIdx.x;
    float s = 0.f;
    for (int i = tid; i < MS; i += 256) s += ent[i];
    red[tid] = s; __syncthreads();
    #pragma unroll
    for (int k = 128; k > 0; k >>= 1) {
        if (tid < k) red[tid] += red[tid + k];
        __syncthreads();
    }
    if (tid == 0) out[0] = red[0] / (float)MS;
}

// ---------------------------------------------------------------------------
extern "C" void kernel_launch(void* const* d_in, const int* in_sizes, int n_in,
                              void* d_out, int out_size)
{
    const float* x    = (const float*)d_in[0];
    const float* Wq   = (const float*)d_in[1];
    const float* bq   = (const float*)d_in[2];
    const float* Wk   = (const float*)d_in[3];
    const float* bk   = (const float*)d_in[4];
    const float* Wv   = (const float*)d_in[5];
    const float* bv   = (const float*)d_in[6];
    const float* temp = (const float*)d_in[7];
    float* out = (float*)d_out;

    __nv_bfloat16 *xh, *xl, *wqh, *wql, *wkh, *wkl, *mth, *mtl, *yh, *yl;
    __half *x16, *xt16, *wvt16, *p16, *z16;
    float *mtp, *p, *cq, *ck, *u, *w, *s0, *ent;
    cudaGetSymbolAddress((void**)&xh,  g_xh);   cudaGetSymbolAddress((void**)&xl,  g_xl);
    cudaGetSymbolAddress((void**)&x16, g_x16);  cudaGetSymbolAddress((void**)&xt16, g_xt16);
    cudaGetSymbolAddress((void**)&wqh, g_wqh);  cudaGetSymbolAddress((void**)&wql, g_wql);
    cudaGetSymbolAddress((void**)&wkh, g_wkh);  cudaGetSymbolAddress((void**)&wkl, g_wkl);
    cudaGetSymbolAddress((void**)&wvt16, g_wvt16);
    cudaGetSymbolAddress((void**)&mtp, g_mtp);
    cudaGetSymbolAddress((void**)&mth, g_mth);  cudaGetSymbolAddress((void**)&mtl, g_mtl);
    cudaGetSymbolAddress((void**)&yh,  g_yh);   cudaGetSymbolAddress((void**)&yl,  g_yl);
    cudaGetSymbolAddress((void**)&p,   g_p);    cudaGetSymbolAddress((void**)&p16, g_p16);
    cudaGetSymbolAddress((void**)&z16, g_z16);
    cudaGetSymbolAddress((void**)&cq,  g_cq);   cudaGetSymbolAddress((void**)&ck,  g_ck);
    cudaGetSymbolAddress((void**)&u,   g_u);    cudaGetSymbolAddress((void**)&w,   g_w);
    cudaGetSymbolAddress((void**)&s0,  g_s0);   cudaGetSymbolAddress((void**)&ent, g_ent);

    cudaFuncSetAttribute(mma_gemm<0>,    cudaFuncAttributeMaxDynamicSharedMemorySize, SMEMB);
    cudaFuncSetAttribute(mma_gemm<2>,    cudaFuncAttributeMaxDynamicSharedMemorySize, SMEMB);
    cudaFuncSetAttribute(mma_gemm_h1<0>, cudaFuncAttributeMaxDynamicSharedMemorySize, SMEM2);
    cudaFuncSetAttribute(mma_gemm_h1<1>, cudaFuncAttributeMaxDynamicSharedMemorySize, SMEM2);

    dim3 tb(32, 8);

    // 1) splits: x -> (bf16 hi/lo, fp16); Wq,Wk -> bf16 hi/lo; Wv -> fp16 transposed
    split_x_kernel<<<(MS*DD/4 + 255)/256, 256>>>(x, xh, xl, x16, MS*DD/4);
    split_kernel<<<(DD*DD/4 + 255)/256, 256>>>(Wq, wqh, wql, DD*DD/4);
    split_kernel<<<(DD*DD/4 + 255)/256, 256>>>(Wk, wkh, wkl, DD*DD/4);
    transpose_f2h<<<dim3(DD/32, DD/32, 1), tb>>>(Wv, wvt16, DD, DD);

    // bias rank-1 terms (exact fp32; zeros in this dataset but handled generally)
    s0_kernel<<<1, 256>>>(bq, bk, s0);
    gemv_cqck<<<DD/8, 256>>>(Wq, Wk, bq, bk, cq, ck);
    gemv_uw<<<MS/8, 256>>>(x, cq, ck, u, w);

    // x^T fp16 per batch (for z GEMM B operand)
    transpose_h<<<dim3(DD/32, SS/32, BB), tb>>>(x16, xt16, SS, DD, (long)SS*DD, (long)DD*SS);

    // 2) M^T = Wk Wq^T, K-split over 4 partials, then reduce+split to bf16
    mma_gemm<0><<<dim3(DD/128, DD/128, 4), 256, SMEMB>>>(
        wkh, wkl, wqh, wql, mtp, nullptr, nullptr,
        DD, 256, DD, DD, 256, 256, (long)DD*DD);
    mt_reduce_split<<<(DD*DD/4 + 255)/256, 256>>>(mtp, mth, mtl, DD*DD/4);

    // 3) y = x M  (NT vs M^T) -> bf16 hi/lo
    mma_gemm<2><<<dim3(DD/128, MS/128, 1), 256, SMEMB>>>(
        xh, xl, mth, mtl, nullptr, yh, yl,
        DD, DD, DD, DD, 0, 0, 0);

    // 4) scores = y x^T per batch -> fp32
    mma_gemm<0><<<dim3(SS/128, SS/128, BB), 256, SMEMB>>>(
        yh, yl, xh, xl, p, nullptr, nullptr,
        SS, DD, DD, DD, (long)SS*DD, (long)SS*DD, (long)SS*SS);

    // 5) softmax + entropy (adds bias rank-1 terms) -> p16
    softmax_ent<<<MS, 256>>>(p, u, w, s0, p16, ent, temp);

    // 6) z = p x per batch (fp16) -> fp16
    mma_gemm_h1<1><<<dim3(DD/128, SS/128, BB), 256, SMEM2>>>(
        p16, xt16, nullptr, z16, nullptr,
        DD, SS, SS, SS, (long)SS*SS, (long)DD*SS, (long)SS*DD);

    // 7) out = z Wv + bv (fp16 MMA, fp32 out)
    mma_gemm_h1<0><<<dim3(DD/128, MS/128, 1), 256, SMEM2>>>(
        z16, wvt16, out, nullptr, bv,
        DD, DD, DD, DD, 0, 0, 0);

    // 8) entropy mean scalar
    ent_reduce<<<1, 256>>>(ent, out + OUT_ELEMS);
}